// round 1
// baseline (speedup 1.0000x reference)
#include <cuda_runtime.h>

// B3-spline à-trous UWT, LEVEL=3.
// Input:  x (B=8, H=1024, W=1024) fp32
// Output: (B, 4, H, W): [w1, w2, w3, c3]
//
// Each level: c_{j+1} = (h ⊗ h) * c_j with dilation 2^j, reflect pad;
//             w_{j+1} = c_j - c_{j+1}.
// One fused separable-conv kernel per level; c planes ping-pong through
// __device__ scratch (no allocations).

#define IMG_H 1024
#define IMG_W 1024
#define NBATCH 8
#define PLANE (IMG_H * IMG_W)

__device__ float g_scratch1[NBATCH * PLANE];
__device__ float g_scratch2[NBATCH * PLANE];

template <int D>
__global__ __launch_bounds__(256) void uwt_level_kernel(
    const float* __restrict__ cin, long cin_bstride,
    float* __restrict__ wout, long wout_bstride,
    float* __restrict__ cout, long cout_bstride)
{
    constexpr int HALO = 2 * D;
    constexpr int TX = 32, TY = 32;
    constexpr int SW = TX + 2 * HALO;   // smem tile width
    constexpr int SH = TY + 2 * HALO;   // smem tile height

    __shared__ float s0[SH][SW];        // raw input tile (with halo)
    __shared__ float s1[TY][SW];        // after vertical conv (horizontal halo kept)

    const int b  = blockIdx.z;
    const int x0 = blockIdx.x * TX;
    const int y0 = blockIdx.y * TY;
    const int tid = threadIdx.x;        // 0..255 (1-D block)

    const float* in = cin + (long)b * cin_bstride;

    // ---- load tile with reflect padding ----
    #pragma unroll
    for (int i = tid; i < SH * SW; i += 256) {
        int ly = i / SW, lx = i % SW;
        int gy = y0 + ly - HALO;
        int gx = x0 + lx - HALO;
        gy = gy < 0 ? -gy : (gy >= IMG_H ? 2 * IMG_H - 2 - gy : gy);
        gx = gx < 0 ? -gx : (gx >= IMG_W ? 2 * IMG_W - 2 - gx : gx);
        s0[ly][lx] = in[gy * IMG_W + gx];
    }
    __syncthreads();

    // ---- vertical 5-tap conv (dilation D) for the TY output rows, all SW cols ----
    #pragma unroll
    for (int i = tid; i < TY * SW; i += 256) {
        int ly = i / SW, lx = i % SW;
        // center at s0 row ly + HALO (= ly + 2D); taps at ly, ly+D, ly+2D, ly+3D, ly+4D
        float v = 0.0625f * (s0[ly][lx] + s0[ly + 4 * D][lx])
                + 0.25f   * (s0[ly + D][lx] + s0[ly + 3 * D][lx])
                + 0.375f  *  s0[ly + 2 * D][lx];
        s1[ly][lx] = v;
    }
    __syncthreads();

    // ---- horizontal 5-tap conv + write w and c_next ----
    float* wo = wout + (long)b * wout_bstride;
    float* co = cout + (long)b * cout_bstride;
    #pragma unroll
    for (int i = tid; i < TY * TX; i += 256) {
        int ly = i / TX, lx = i % TX;
        float v = 0.0625f * (s1[ly][lx] + s1[ly][lx + 4 * D])
                + 0.25f   * (s1[ly][lx + D] + s1[ly][lx + 3 * D])
                + 0.375f  *  s1[ly][lx + 2 * D];
        const int gy = y0 + ly, gx = x0 + lx;
        const float c = s0[ly + HALO][lx + HALO];
        wo[gy * IMG_W + gx] = c - v;   // wavelet detail
        co[gy * IMG_W + gx] = v;       // next coarse plane
    }
}

extern "C" void kernel_launch(void* const* d_in, const int* in_sizes, int n_in,
                              void* d_out, int out_size)
{
    (void)in_sizes; (void)n_in; (void)out_size;
    const float* x = (const float*)d_in[0];
    float* out = (float*)d_out;

    float *c1, *c2;
    cudaGetSymbolAddress((void**)&c1, g_scratch1);
    cudaGetSymbolAddress((void**)&c2, g_scratch2);

    dim3 block(256, 1, 1);
    dim3 grid(IMG_W / 32, IMG_H / 32, NBATCH);

    const long IN_BS  = (long)PLANE;       // (B, H, W) batch stride
    const long OUT_BS = 4L * PLANE;        // (B, 4, H, W) batch stride

    // Level 0: d=1.  cin = x, w -> out slice 0, c1 -> scratch1
    uwt_level_kernel<1><<<grid, block>>>(x, IN_BS,
                                         out + 0L * PLANE, OUT_BS,
                                         c1, IN_BS);
    // Level 1: d=2.  cin = scratch1, w -> out slice 1, c2 -> scratch2
    uwt_level_kernel<2><<<grid, block>>>(c1, IN_BS,
                                         out + 1L * PLANE, OUT_BS,
                                         c2, IN_BS);
    // Level 2: d=4.  cin = scratch2, w -> out slice 2, c3 -> out slice 3
    uwt_level_kernel<4><<<grid, block>>>(c2, IN_BS,
                                         out + 2L * PLANE, OUT_BS,
                                         out + 3L * PLANE, OUT_BS);
}

// round 2
// speedup vs baseline: 1.2572x; 1.2572x over previous
#include <cuda_runtime.h>

// B3-spline à-trous UWT, LEVEL=3.  x:(8,1024,1024) f32 -> (8,4,1024,1024) f32
// Per level j (d=2^j): c_{j+1} = (h x h)*c_j (reflect pad), w_{j+1} = c_j - c_{j+1}.
// One fused separable kernel per level, float4 vectorized, interior fast path.

#define IMG_H 1024
#define IMG_W 1024
#define NBATCH 8
#define PLANE (IMG_H * IMG_W)

__device__ float g_scratch1[NBATCH * PLANE];
__device__ float g_scratch2[NBATCH * PLANE];

template <int D>
__global__ __launch_bounds__(256) void uwt_level_kernel(
    const float* __restrict__ cin,
    float* __restrict__ wout, long wbs,
    float* __restrict__ cout, long cbs)
{
    constexpr int HALO = 2 * D;                    // 2, 4, 8
    constexpr int TX = 64, TY = 32;
    constexpr int PADX = ((HALO + 3) / 4) * 4;     // 4, 4, 8 (float4-aligned x halo)
    constexpr int PAD4 = PADX / 4;
    constexpr int LW  = TX + 2 * PADX;             // 72, 72, 80
    constexpr int LW4 = LW / 4;                    // 18, 18, 20
    constexpr int SH  = TY + 2 * HALO;             // 36, 40, 48
    constexpr int RSTRIDE = 256 / LW4;             // 14, 14, 12
    constexpr int WORKERS = RSTRIDE * LW4;         // 252, 252, 240

    __shared__ __align__(16) float s0[SH][LW];     // raw tile (+halo)
    __shared__ __align__(16) float s1[TY][LW];     // after vertical conv

    const int b   = blockIdx.z;
    const int x0  = blockIdx.x * TX;
    const int y0  = blockIdx.y * TY;
    const int tid = threadIdx.x;

    const float* in = cin + (long)b * PLANE;

    const bool interior = (x0 >= PADX) && (x0 + TX + PADX <= IMG_W)
                       && (y0 >= HALO) && (y0 + TY + HALO <= IMG_H);

    const int c4 = tid % LW4;   // float4 column (computed once)
    const int r0 = tid / LW4;   // starting row

    // ---------------- load tile ----------------
    if (interior) {
        if (tid < WORKERS) {
            const float4* inr = (const float4*)(in + (long)(y0 - HALO) * IMG_W
                                                   + (x0 - PADX));
            #pragma unroll
            for (int r = r0; r < SH; r += RSTRIDE)
                ((float4*)s0[r])[c4] = inr[(long)r * (IMG_W / 4) + c4];
        }
    } else {
        // border block: scalar loads with reflect mapping
        for (int i = tid; i < SH * LW; i += 256) {
            int r = i / LW, c = i - r * LW;
            int gy = y0 + r - HALO;
            int gx = x0 + c - PADX;
            gy = gy < 0 ? -gy : (gy >= IMG_H ? 2 * IMG_H - 2 - gy : gy);
            gx = gx < 0 ? -gx : (gx >= IMG_W ? 2 * IMG_W - 2 - gx : gx);
            s0[r][c] = in[gy * IMG_W + gx];
        }
    }
    __syncthreads();

    // ---------------- vertical 5-tap (dilation D), vectorized ----------------
    if (tid < WORKERS) {
        #pragma unroll
        for (int r = r0; r < TY; r += RSTRIDE) {
            float4 a0 = ((const float4*)s0[r        ])[c4];
            float4 a1 = ((const float4*)s0[r +     D])[c4];
            float4 a2 = ((const float4*)s0[r + 2 * D])[c4];
            float4 a3 = ((const float4*)s0[r + 3 * D])[c4];
            float4 a4 = ((const float4*)s0[r + 4 * D])[c4];
            float4 v;
            v.x = 0.0625f * (a0.x + a4.x) + 0.25f * (a1.x + a3.x) + 0.375f * a2.x;
            v.y = 0.0625f * (a0.y + a4.y) + 0.25f * (a1.y + a3.y) + 0.375f * a2.y;
            v.z = 0.0625f * (a0.z + a4.z) + 0.25f * (a1.z + a3.z) + 0.375f * a2.z;
            v.w = 0.0625f * (a0.w + a4.w) + 0.25f * (a1.w + a3.w) + 0.375f * a2.w;
            ((float4*)s1[r])[c4] = v;
        }
    }
    __syncthreads();

    // ---------------- horizontal 5-tap + write w, c_next ----------------
    const int oc4 = tid & 15;    // output float4 column, 0..15
    const int rr  = tid >> 4;    // 0..15
    float* wo = wout + (long)b * wbs;
    float* co = cout + (long)b * cbs;

    #pragma unroll
    for (int rI = 0; rI < 2; rI++) {
        const int r = rr + rI * 16;
        const float4* row = (const float4*)s1[r];
        float4 v;
        if constexpr (D == 4) {
            // taps are float4-aligned: offsets -8,-4,0,+4,+8 floats
            float4 A0 = row[oc4], A1 = row[oc4 + 1], A2 = row[oc4 + 2],
                   A3 = row[oc4 + 3], A4 = row[oc4 + 4];
            v.x = 0.0625f * (A0.x + A4.x) + 0.25f * (A1.x + A3.x) + 0.375f * A2.x;
            v.y = 0.0625f * (A0.y + A4.y) + 0.25f * (A1.y + A3.y) + 0.375f * A2.y;
            v.z = 0.0625f * (A0.z + A4.z) + 0.25f * (A1.z + A3.z) + 0.375f * A2.z;
            v.w = 0.0625f * (A0.w + A4.w) + 0.25f * (A1.w + A3.w) + 0.375f * A2.w;
        } else {
            // load 12 contiguous floats [c-4, c+8) into registers, pick taps
            float4 B0 = row[oc4], B1 = row[oc4 + 1], B2 = row[oc4 + 2];
            float f[12] = {B0.x, B0.y, B0.z, B0.w,
                           B1.x, B1.y, B1.z, B1.w,
                           B2.x, B2.y, B2.z, B2.w};
            v.x = 0.0625f * (f[4 - 2 * D] + f[4 + 2 * D])
                + 0.25f   * (f[4 - D]     + f[4 + D])
                + 0.375f  *  f[4];
            v.y = 0.0625f * (f[5 - 2 * D] + f[5 + 2 * D])
                + 0.25f   * (f[5 - D]     + f[5 + D])
                + 0.375f  *  f[5];
            v.z = 0.0625f * (f[6 - 2 * D] + f[6 + 2 * D])
                + 0.25f   * (f[6 - D]     + f[6 + D])
                + 0.375f  *  f[6];
            v.w = 0.0625f * (f[7 - 2 * D] + f[7 + 2 * D])
                + 0.25f   * (f[7 - D]     + f[7 + D])
                + 0.375f  *  f[7];
        }
        float4 cc = ((const float4*)s0[r + HALO])[oc4 + PAD4];
        float4 w4 = make_float4(cc.x - v.x, cc.y - v.y, cc.z - v.z, cc.w - v.w);
        const long o = (long)(y0 + r) * (IMG_W / 4) + (x0 / 4) + oc4;
        ((float4*)wo)[o] = w4;
        ((float4*)co)[o] = v;
    }
}

extern "C" void kernel_launch(void* const* d_in, const int* in_sizes, int n_in,
                              void* d_out, int out_size)
{
    (void)in_sizes; (void)n_in; (void)out_size;
    const float* x = (const float*)d_in[0];
    float* out = (float*)d_out;

    float *c1, *c2;
    cudaGetSymbolAddress((void**)&c1, g_scratch1);
    cudaGetSymbolAddress((void**)&c2, g_scratch2);

    dim3 block(256, 1, 1);
    dim3 grid(IMG_W / 64, IMG_H / 32, NBATCH);

    const long IN_BS  = (long)PLANE;
    const long OUT_BS = 4L * PLANE;

    uwt_level_kernel<1><<<grid, block>>>(x,  out + 0L * PLANE, OUT_BS, c1, IN_BS);
    uwt_level_kernel<2><<<grid, block>>>(c1, out + 1L * PLANE, OUT_BS, c2, IN_BS);
    uwt_level_kernel<4><<<grid, block>>>(c2, out + 2L * PLANE, OUT_BS,
                                             out + 3L * PLANE, OUT_BS);
}